// round 4
// baseline (speedup 1.0000x reference)
#include <cuda_runtime.h>
#include <cuda_bf16.h>

// Fixed problem constants:
//   SIGMA=8 -> 1/(2*sigma^2)=1/128, C_SIZE=512, STRIDE=8 -> 64x64 grid,
//   cood[k]=8k+4, B=16, N=512, BG_RATIO=0.15, EPS=1e-5
//   out[b, p, i*64+j], p in [0,512], fp32, [16, 513, 4096]

#define CGRID   64
#define NPTS    512
#define PCHUNK  32
#define NCHUNK  (NPTS / PCHUNK)     // 16
#define BFIX    16
#define MPIX    (CGRID * CGRID)     // 4096
#define KINV    (1.0f / 128.0f)

// Static scratch (no runtime allocation allowed)
__device__ float g_Ex[BFIX * NPTS * CGRID];      // 2 MB: exp(-(x_p-cood_j)^2/128)
__device__ float g_Ey[BFIX * NPTS * CGRID];      // 2 MB: exp(-(y_p-cood_i)^2/128)
__device__ float g_psum[BFIX * NCHUNK * MPIX];   // 4 MB per-chunk partial sums
__device__ float g_pmax[BFIX * NCHUNK * MPIX];   // 4 MB per-chunk max products
__device__ float g_invt[BFIX * MPIX];            // 1/denominator per pixel

// ---------------------------------------------------------------------------
// K0: build separable exp tables. 2 * 16*512*64 = 1M exps.
// ---------------------------------------------------------------------------
__global__ __launch_bounds__(256)
void k_tables(const float* __restrict__ points)
{
    int idx = blockIdx.x * 256 + threadIdx.x;        // 0 .. 2^20-1
    int t  = idx >> 19;                               // 0 = Ex (x), 1 = Ey (y)
    int r  = idx & ((1 << 19) - 1);                   // b*512*64 + p*64 + cell
    int bp = r >> 6;
    int cell = r & 63;
    float coord = points[bp * 2 + t];                 // x or y of point (b,p)
    float d = coord - (float)(cell * 8 + 4);
    float e = __expf(-d * d * KINV);
    if (t) g_Ey[r] = e; else g_Ex[r] = e;
}

// ---------------------------------------------------------------------------
// K1: per (b, chunk, 16-row tile): partial exp-sum + max product.
//     min-distance recovered later as -128*ln(max product).
//     No smem, no syncs — pure LDG(L1/L2-hit) + FMA.
// ---------------------------------------------------------------------------
__global__ __launch_bounds__(256)
void k_partial()
{
    const int b   = blockIdx.z;
    const int c   = blockIdx.y;
    const int i0  = blockIdx.x * 16;
    const int tid = threadIdx.x;
    const int ti  = tid >> 4;      // 0..15 row in tile
    const int jg  = tid & 15;      // owns j = jg*4 + {0..3}
    const int i   = i0 + ti;

    const float4* __restrict__ Ex4 = (const float4*)(g_Ex + (b * NPTS + c * PCHUNK) * CGRID);
    const float*  __restrict__ Eyp = g_Ey + (b * NPTS + c * PCHUNK) * CGRID + i;

    float4 sum = make_float4(0.f, 0.f, 0.f, 0.f);
    float4 mx  = make_float4(0.f, 0.f, 0.f, 0.f);

    #pragma unroll 8
    for (int p = 0; p < PCHUNK; ++p) {
        float  ey = __ldg(Eyp + p * CGRID);
        float4 ex = __ldg(Ex4 + p * 16 + jg);
        float p0 = ey * ex.x;
        float p1 = ey * ex.y;
        float p2 = ey * ex.z;
        float p3 = ey * ex.w;
        sum.x += p0; sum.y += p1; sum.z += p2; sum.w += p3;
        mx.x = fmaxf(mx.x, p0); mx.y = fmaxf(mx.y, p1);
        mx.z = fmaxf(mx.z, p2); mx.w = fmaxf(mx.w, p3);
    }

    int o = (b * NCHUNK + c) * MPIX + i * CGRID + jg * 4;
    *(float4*)(g_psum + o) = sum;
    *(float4*)(g_pmax + o) = mx;
}

// ---------------------------------------------------------------------------
// K2: reduce chunk partials -> invt per pixel; write background plane p=512.
// ---------------------------------------------------------------------------
__global__ __launch_bounds__(256)
void k_combine(const float* __restrict__ st_sizes, float* __restrict__ out)
{
    int idx = blockIdx.x * 256 + threadIdx.x;       // over BFIX*MPIX/4 = 16384
    int b = idx >> 10;                               // MPIX/4 = 1024
    int r = idx & 1023;

    const float4* ps = (const float4*)g_psum;
    const float4* pm = (const float4*)g_pmax;
    int base = b * NCHUNK * 1024 + r;

    float4 sum = make_float4(0.f, 0.f, 0.f, 0.f);
    float4 mx  = make_float4(0.f, 0.f, 0.f, 0.f);
    #pragma unroll
    for (int c = 0; c < NCHUNK; ++c) {
        float4 s = ps[base + c * 1024];
        float4 m = pm[base + c * 1024];
        sum.x += s.x; sum.y += s.y; sum.z += s.z; sum.w += s.w;
        mx.x = fmaxf(mx.x, m.x); mx.y = fmaxf(mx.y, m.y);
        mx.z = fmaxf(mx.z, m.z); mx.w = fmaxf(mx.w, m.w);
    }

    float sc = st_sizes[b] * 0.15f;
    float ss = sc * sc;
    float4 invt, bgp;
    {
        float mind = -128.0f * __logf(fmaxf(mx.x, 1e-38f));
        float ebg = __expf(-(ss / (mind + 1e-5f)) * KINV);
        float iv = 1.0f / (sum.x + ebg); invt.x = iv; bgp.x = ebg * iv;
    }
    {
        float mind = -128.0f * __logf(fmaxf(mx.y, 1e-38f));
        float ebg = __expf(-(ss / (mind + 1e-5f)) * KINV);
        float iv = 1.0f / (sum.y + ebg); invt.y = iv; bgp.y = ebg * iv;
    }
    {
        float mind = -128.0f * __logf(fmaxf(mx.z, 1e-38f));
        float ebg = __expf(-(ss / (mind + 1e-5f)) * KINV);
        float iv = 1.0f / (sum.z + ebg); invt.z = iv; bgp.z = ebg * iv;
    }
    {
        float mind = -128.0f * __logf(fmaxf(mx.w, 1e-38f));
        float ebg = __expf(-(ss / (mind + 1e-5f)) * KINV);
        float iv = 1.0f / (sum.w + ebg); invt.w = iv; bgp.w = ebg * iv;
    }

    ((float4*)g_invt)[b * 1024 + r] = invt;
    __stcs(((float4*)out) + (b * 513 + 512) * 1024 + r, bgp);  // background plane
}

// ---------------------------------------------------------------------------
// K3: normalized streaming writes for the 512 point planes.
// ---------------------------------------------------------------------------
__global__ __launch_bounds__(256)
void k_write(float* __restrict__ out)
{
    const int b   = blockIdx.z;
    const int c   = blockIdx.y;
    const int i0  = blockIdx.x * 16;
    const int tid = threadIdx.x;
    const int ti  = tid >> 4;
    const int jg  = tid & 15;
    const int i   = i0 + ti;

    const float4* __restrict__ Ex4 = (const float4*)(g_Ex + (b * NPTS + c * PCHUNK) * CGRID);
    const float*  __restrict__ Eyp = g_Ey + (b * NPTS + c * PCHUNK) * CGRID + i;

    float4 invt = ((const float4*)g_invt)[b * 1024 + i * 16 + jg];
    float* op = out + ((size_t)b * 513 + c * PCHUNK) * MPIX + i * CGRID + jg * 4;

    #pragma unroll 8
    for (int p = 0; p < PCHUNK; ++p) {
        float  ey = __ldg(Eyp + p * CGRID);
        float4 ex = __ldg(Ex4 + p * 16 + jg);
        float4 v;
        v.x = (ey * ex.x) * invt.x;
        v.y = (ey * ex.y) * invt.y;
        v.z = (ey * ex.z) * invt.z;
        v.w = (ey * ex.w) * invt.w;
        __stcs((float4*)(op + (size_t)p * MPIX), v);
    }
}

// ---------------------------------------------------------------------------
extern "C" void kernel_launch(void* const* d_in, const int* in_sizes, int n_in,
                              void* d_out, int out_size)
{
    const float* points   = (const float*)d_in[0];   // [16, 512, 2]
    const float* st_sizes = (const float*)d_in[1];   // [16]
    float* out = (float*)d_out;                      // [16, 513, 4096]

    k_tables<<<(2 * BFIX * NPTS * CGRID) / 256, 256>>>(points);
    dim3 g1(CGRID / 16, NCHUNK, BFIX);               // (4, 16, 16) = 1024 blocks
    k_partial<<<g1, 256>>>();
    k_combine<<<(BFIX * MPIX / 4) / 256, 256>>>(st_sizes, out);
    k_write<<<g1, 256>>>(out);
}

// round 5
// speedup vs baseline: 1.2321x; 1.2321x over previous
#include <cuda_runtime.h>
#include <cuda_bf16.h>

// Fixed problem constants:
//   SIGMA=8 -> 1/(2*sigma^2)=1/128, C_SIZE=512, STRIDE=8 -> 64x64 grid,
//   cood[k]=8k+4, B=16, N=512, BG_RATIO=0.15, EPS=1e-5
//   out[b, p, i*64+j], p in [0,512], fp32, [16, 513, 4096]

#define CGRID   64
#define NPTS    512
#define PCHUNK  32
#define NCHUNK  (NPTS / PCHUNK)     // 16
#define BFIX    16
#define MPIX    (CGRID * CGRID)     // 4096
#define KINV    (1.0f / 128.0f)

// Static scratch (no runtime allocation allowed)
__device__ float g_psum[BFIX * NCHUNK * MPIX];   // 4 MB per-chunk partial sums
__device__ float g_pmax[BFIX * NCHUNK * MPIX];   // 4 MB per-chunk max products
__device__ float g_invt[BFIX * MPIX];            // 1/denominator per pixel

// ---------------------------------------------------------------------------
// K1: per (b, chunk, 16-row tile): partial exp-sum + max product (smem tables).
//     min-distance recovered later as -128*ln(max product).
// ---------------------------------------------------------------------------
__global__ __launch_bounds__(256)
void k_partial(const float* __restrict__ points)
{
    const int b   = blockIdx.z;
    const int c   = blockIdx.y;
    const int i0  = blockIdx.x * 16;
    const int tid = threadIdx.x;
    const int ti  = tid >> 4;      // 0..15 row in tile
    const int jg  = tid & 15;      // owns j = jg*4 + {0..3}

    __shared__ float2 pts_s[PCHUNK];            // 256 B
    __shared__ float  Ex_s[PCHUNK * CGRID];     // 8 KB  [p][j]
    __shared__ float  Ey_s[16 * PCHUNK];        // 2 KB  [ti][p]

    const float2* ptb = (const float2*)points + b * NPTS + c * PCHUNK;
    if (tid < PCHUNK) pts_s[tid] = ptb[tid];
    __syncthreads();

    #pragma unroll
    for (int k = 0; k < (PCHUNK * CGRID) / 256; ++k) {   // 8 iters
        int idx = tid + k * 256;
        int p = idx >> 6, jj = idx & 63;
        float dx = pts_s[p].x - (float)(jj * 8 + 4);
        Ex_s[idx] = __expf(-dx * dx * KINV);
    }
    #pragma unroll
    for (int k = 0; k < (16 * PCHUNK) / 256; ++k) {      // 2 iters
        int idx = tid + k * 256;
        int ii = idx >> 5, p = idx & (PCHUNK - 1);
        float dy = pts_s[p].y - (float)((i0 + ii) * 8 + 4);
        Ey_s[idx] = __expf(-dy * dy * KINV);
    }
    __syncthreads();

    float4 sum = make_float4(0.f, 0.f, 0.f, 0.f);
    float4 mx  = make_float4(0.f, 0.f, 0.f, 0.f);
    const float4* Ex4 = (const float4*)Ex_s;

    #pragma unroll 8
    for (int p = 0; p < PCHUNK; ++p) {
        float  ey = Ey_s[ti * PCHUNK + p];
        float4 ex = Ex4[p * 16 + jg];
        float p0 = ey * ex.x;
        float p1 = ey * ex.y;
        float p2 = ey * ex.z;
        float p3 = ey * ex.w;
        sum.x += p0; sum.y += p1; sum.z += p2; sum.w += p3;
        mx.x = fmaxf(mx.x, p0); mx.y = fmaxf(mx.y, p1);
        mx.z = fmaxf(mx.z, p2); mx.w = fmaxf(mx.w, p3);
    }

    int o = (b * NCHUNK + c) * MPIX + (i0 + ti) * CGRID + jg * 4;
    *(float4*)(g_psum + o) = sum;
    *(float4*)(g_pmax + o) = mx;
}

// ---------------------------------------------------------------------------
// K2: reduce chunk partials -> invt per pixel; write background plane p=512.
// ---------------------------------------------------------------------------
__global__ __launch_bounds__(256)
void k_combine(const float* __restrict__ st_sizes, float* __restrict__ out)
{
    int idx = blockIdx.x * 256 + threadIdx.x;       // over BFIX*MPIX/4 = 16384
    int b = idx >> 10;                               // MPIX/4 = 1024
    int r = idx & 1023;

    const float4* ps = (const float4*)g_psum;
    const float4* pm = (const float4*)g_pmax;
    int base = b * NCHUNK * 1024 + r;

    float4 sum = make_float4(0.f, 0.f, 0.f, 0.f);
    float4 mx  = make_float4(0.f, 0.f, 0.f, 0.f);
    #pragma unroll
    for (int c = 0; c < NCHUNK; ++c) {
        float4 s = ps[base + c * 1024];
        float4 m = pm[base + c * 1024];
        sum.x += s.x; sum.y += s.y; sum.z += s.z; sum.w += s.w;
        mx.x = fmaxf(mx.x, m.x); mx.y = fmaxf(mx.y, m.y);
        mx.z = fmaxf(mx.z, m.z); mx.w = fmaxf(mx.w, m.w);
    }

    float sc = st_sizes[b] * 0.15f;
    float ss = sc * sc;
    float4 invt, bgp;
    {
        float mind = -128.0f * __logf(fmaxf(mx.x, 1e-38f));
        float ebg = __expf(-(ss / (mind + 1e-5f)) * KINV);
        float iv = 1.0f / (sum.x + ebg); invt.x = iv; bgp.x = ebg * iv;
    }
    {
        float mind = -128.0f * __logf(fmaxf(mx.y, 1e-38f));
        float ebg = __expf(-(ss / (mind + 1e-5f)) * KINV);
        float iv = 1.0f / (sum.y + ebg); invt.y = iv; bgp.y = ebg * iv;
    }
    {
        float mind = -128.0f * __logf(fmaxf(mx.z, 1e-38f));
        float ebg = __expf(-(ss / (mind + 1e-5f)) * KINV);
        float iv = 1.0f / (sum.z + ebg); invt.z = iv; bgp.z = ebg * iv;
    }
    {
        float mind = -128.0f * __logf(fmaxf(mx.w, 1e-38f));
        float ebg = __expf(-(ss / (mind + 1e-5f)) * KINV);
        float iv = 1.0f / (sum.w + ebg); invt.w = iv; bgp.w = ebg * iv;
    }

    ((float4*)g_invt)[b * 1024 + r] = invt;
    __stcs(((float4*)out) + (b * 513 + 512) * 1024 + r, bgp);  // background plane
}

// ---------------------------------------------------------------------------
// K3: normalized writes. Block = (b, group of 8 planes) -> each block writes
//     a fully CONTIGUOUS 128 KB span of out. Per-plane Ex/Ey (64+64 floats)
//     recomputed in-block; invt held in registers (float4 x4 per thread).
// ---------------------------------------------------------------------------
#define PGRP 8

__global__ __launch_bounds__(256)
void k_write(const float* __restrict__ points, float* __restrict__ out)
{
    const int b   = blockIdx.x >> 6;            // 0..15
    const int pg  = blockIdx.x & 63;            // plane group: p = pg*8 + pl
    const int tid = threadIdx.x;

    __shared__ float Ex_s[PGRP][CGRID];         // 2 KB
    __shared__ float Ey_s[PGRP][CGRID];         // 2 KB

    // Fill per-plane Ex/Ey rows: 8 planes * 64 cells * 2 tables = 1024 exps.
    #pragma unroll
    for (int k = 0; k < 4; ++k) {
        int idx  = tid + k * 256;               // 0..1023
        int pl   = idx >> 7;                    // 0..7
        int rest = idx & 127;
        int t    = rest >> 6;                   // 0: Ex (x), 1: Ey (y)
        int cell = rest & 63;
        int p    = pg * PGRP + pl;
        float coord = points[(b * NPTS + p) * 2 + t];
        float d = coord - (float)(cell * 8 + 4);
        float e = __expf(-d * d * KINV);
        if (t) Ey_s[pl][cell] = e; else Ex_s[pl][cell] = e;
    }

    // invt for this image: each thread holds 4 float4 (covers its 4 f-slots).
    const float4* iv4 = (const float4*)g_invt + b * 1024;
    float4 invt[4];
    #pragma unroll
    for (int k = 0; k < 4; ++k)
        invt[k] = __ldg(iv4 + tid + k * 256);

    __syncthreads();

    float4* op = (float4*)out + ((size_t)b * 513 + pg * PGRP) * 1024;

    #pragma unroll
    for (int pl = 0; pl < PGRP; ++pl) {
        const float4* Ex4 = (const float4*)Ex_s[pl];
        #pragma unroll
        for (int k = 0; k < 4; ++k) {
            int f  = tid + k * 256;             // float4 index within plane
            int i  = f >> 4;
            int jg = f & 15;
            float  ey = Ey_s[pl][i];
            float4 ex = Ex4[jg];
            float4 v;
            v.x = (ey * ex.x) * invt[k].x;
            v.y = (ey * ex.y) * invt[k].y;
            v.z = (ey * ex.z) * invt[k].z;
            v.w = (ey * ex.w) * invt[k].w;
            __stcs(op + (size_t)pl * 1024 + f, v);
        }
    }
}

// ---------------------------------------------------------------------------
extern "C" void kernel_launch(void* const* d_in, const int* in_sizes, int n_in,
                              void* d_out, int out_size)
{
    const float* points   = (const float*)d_in[0];   // [16, 512, 2]
    const float* st_sizes = (const float*)d_in[1];   // [16]
    float* out = (float*)d_out;                      // [16, 513, 4096]

    dim3 g1(CGRID / 16, NCHUNK, BFIX);               // (4, 16, 16) = 1024 blocks
    k_partial<<<g1, 256>>>(points);
    k_combine<<<(BFIX * MPIX / 4) / 256, 256>>>(st_sizes, out);
    k_write<<<BFIX * (NPTS / PGRP), 256>>>(points, out);   // 16*64 = 1024 blocks
}